// round 3
// baseline (speedup 1.0000x reference)
#include <cuda_runtime.h>
#include <cstddef>

#define RLA_EPS 1e-6f

__device__ __forceinline__ float elu1(float x) {
    // elu(x) + 1  ==  x>0 ? x+1 : exp(x)
    return x > 0.0f ? x + 1.0f : __expf(x);
}

// One CTA per (b,n) pair. 256 threads = 4 d-subgroups x 64 float4 columns.
// Phase 1: Q/K feature maps, Zi_new, shuffle-reduced normalizer Z.
// Phase 2: stream Si tile [D, M] once, in batches of 16 contiguous rows
//          (16 KB): 4 loads/thread -> fma -> 4 stores/thread. Coarse
//          same-direction bursts for the DRAM controller, guaranteed MLP=4.
__global__ __launch_bounds__(256, 7)
void rla_kernel(const float* __restrict__ q,
                const float* __restrict__ k,
                const float* __restrict__ v,
                const float* __restrict__ Si,
                const float* __restrict__ Zi,
                float* __restrict__ outV,    // [BN, M]
                float* __restrict__ outSi,   // [BN, D, M]
                float* __restrict__ outZi,   // [BN, D]
                int D, int M)
{
    const int bn  = blockIdx.x;
    const int tid = threadIdx.x;

    __shared__ float sQ[256];
    __shared__ float sK[256];
    __shared__ float swred[8];
    __shared__ float sZ;
    __shared__ float4 sacc[256];

    const size_t rowD = (size_t)bn * D;
    const size_t rowM = (size_t)bn * M;
    const size_t tile = (size_t)bn * D * M;

    // ---------------- Phase 1: feature maps + normalizer ----------------
    const int lane32 = tid & 31;
    const int warp   = tid >> 5;

    float part = 0.0f;
    for (int d = tid; d < D; d += blockDim.x) {
        float Qd = elu1(q[rowD + d]);
        float Kd = elu1(k[rowD + d]);
        float zn = Zi[rowD + d] + Kd;
        outZi[rowD + d] = zn;
        sQ[d] = Qd;
        sK[d] = Kd;
        part += Qd * zn;
    }
    #pragma unroll
    for (int o = 16; o > 0; o >>= 1)
        part += __shfl_down_sync(0xffffffffu, part, o);
    if (lane32 == 0) swred[warp] = part;
    __syncthreads();
    if (tid == 0) {
        float s = 0.0f;
        #pragma unroll
        for (int w = 0; w < 8; w++) s += swred[w];
        sZ = 1.0f / (s + RLA_EPS);
    }
    __syncthreads();

    // ---------------- Phase 2: batched stream of Si ----------------------
    const int M4   = M >> 2;      // float4 columns per row (64)
    const int lane = tid & 63;    // column
    const int ty   = tid >> 6;    // d-subgroup 0..3

    const float4* Si4 = (const float4*)(Si    + tile);
    float4*       So4 = (float4*)      (outSi + tile);
    const float4* v4p = (const float4*)(v     + rowM);
    float4*       V4  = (float4*)      (outV  + rowM);

    const float4 v4 = v4p[lane];
    float4 acc = make_float4(0.f, 0.f, 0.f, 0.f);

    // Thread handles rows d = ty + 4*j. Batch 4 j's: CTA covers 16
    // contiguous rows (16 KB) per batch: load burst -> compute -> store burst.
    for (int d0 = ty; d0 < D; d0 += 16) {
        float4 s0 = __ldcs(&Si4[(size_t)(d0     ) * M4 + lane]);
        float4 s1 = __ldcs(&Si4[(size_t)(d0 +  4) * M4 + lane]);
        float4 s2 = __ldcs(&Si4[(size_t)(d0 +  8) * M4 + lane]);
        float4 s3 = __ldcs(&Si4[(size_t)(d0 + 12) * M4 + lane]);

        {
            const float kd = sK[d0], qd = sQ[d0];
            s0.x = fmaf(kd, v4.x, s0.x); s0.y = fmaf(kd, v4.y, s0.y);
            s0.z = fmaf(kd, v4.z, s0.z); s0.w = fmaf(kd, v4.w, s0.w);
            acc.x = fmaf(qd, s0.x, acc.x); acc.y = fmaf(qd, s0.y, acc.y);
            acc.z = fmaf(qd, s0.z, acc.z); acc.w = fmaf(qd, s0.w, acc.w);
        }
        {
            const float kd = sK[d0 + 4], qd = sQ[d0 + 4];
            s1.x = fmaf(kd, v4.x, s1.x); s1.y = fmaf(kd, v4.y, s1.y);
            s1.z = fmaf(kd, v4.z, s1.z); s1.w = fmaf(kd, v4.w, s1.w);
            acc.x = fmaf(qd, s1.x, acc.x); acc.y = fmaf(qd, s1.y, acc.y);
            acc.z = fmaf(qd, s1.z, acc.z); acc.w = fmaf(qd, s1.w, acc.w);
        }
        {
            const float kd = sK[d0 + 8], qd = sQ[d0 + 8];
            s2.x = fmaf(kd, v4.x, s2.x); s2.y = fmaf(kd, v4.y, s2.y);
            s2.z = fmaf(kd, v4.z, s2.z); s2.w = fmaf(kd, v4.w, s2.w);
            acc.x = fmaf(qd, s2.x, acc.x); acc.y = fmaf(qd, s2.y, acc.y);
            acc.z = fmaf(qd, s2.z, acc.z); acc.w = fmaf(qd, s2.w, acc.w);
        }
        {
            const float kd = sK[d0 + 12], qd = sQ[d0 + 12];
            s3.x = fmaf(kd, v4.x, s3.x); s3.y = fmaf(kd, v4.y, s3.y);
            s3.z = fmaf(kd, v4.z, s3.z); s3.w = fmaf(kd, v4.w, s3.w);
            acc.x = fmaf(qd, s3.x, acc.x); acc.y = fmaf(qd, s3.y, acc.y);
            acc.z = fmaf(qd, s3.z, acc.z); acc.w = fmaf(qd, s3.w, acc.w);
        }

        __stcs(&So4[(size_t)(d0     ) * M4 + lane], s0);
        __stcs(&So4[(size_t)(d0 +  4) * M4 + lane], s1);
        __stcs(&So4[(size_t)(d0 +  8) * M4 + lane], s2);
        __stcs(&So4[(size_t)(d0 + 12) * M4 + lane], s3);
    }

    // ---------------- V reduction across the 4 d-subgroups ---------------
    sacc[tid] = acc;
    __syncthreads();
    if (ty == 0) {
        const float Z = sZ;
        float4 a0 = sacc[lane];
        float4 a1 = sacc[lane + 64];
        float4 a2 = sacc[lane + 128];
        float4 a3 = sacc[lane + 192];
        float4 out;
        out.x = Z * (a0.x + a1.x + a2.x + a3.x);
        out.y = Z * (a0.y + a1.y + a2.y + a3.y);
        out.z = Z * (a0.z + a1.z + a2.z + a3.z);
        out.w = Z * (a0.w + a1.w + a2.w + a3.w);
        V4[lane] = out;
    }
}

extern "C" void kernel_launch(void* const* d_in, const int* in_sizes, int n_in,
                              void* d_out, int out_size)
{
    const float* q  = (const float*)d_in[0];
    const float* k  = (const float*)d_in[1];
    const float* v  = (const float*)d_in[2];
    const float* Si = (const float*)d_in[3];
    const float* Zi = (const float*)d_in[4];

    const long long nQ  = in_sizes[0];  // BN * D
    const long long nV  = in_sizes[2];  // BN * M
    const long long nSi = in_sizes[3];  // BN * D * M

    const int D  = (int)(nSi / nV);
    const int M  = (int)(nSi / nQ);
    const int BN = (int)(nQ / D);

    float* out   = (float*)d_out;
    float* outV  = out;                 // [BN, M]
    float* outSi = out + nV;            // [BN, D, M]
    float* outZi = out + nV + nSi;      // [BN, D]

    rla_kernel<<<BN, 256>>>(q, k, v, Si, Zi, outV, outSi, outZi, D, M);
}

// round 4
// speedup vs baseline: 1.2171x; 1.2171x over previous
#include <cuda_runtime.h>
#include <cstddef>

#define RLA_EPS 1e-6f

__device__ __forceinline__ float elu1(float x) {
    // elu(x) + 1  ==  x>0 ? x+1 : exp(x)
    return x > 0.0f ? x + 1.0f : __expf(x);
}

// One CTA per (b,n) pair. 256 threads.
// Phase 1: Q/K feature maps, Zi_new, block-reduced normalizer Z.
// Phase 2: stream Si tile [D, M] once as float4, rank-1 update, accumulate V.
// Loads are evict-first (.cs, no reuse). Stores use DEFAULT caching so the
// 126MB L2 batches the write stream into coarse same-direction DRAM bursts
// instead of fine-grained read/write interleave (bus-turnaround theory).
__global__ __launch_bounds__(256, 8)
void rla_kernel(const float* __restrict__ q,
                const float* __restrict__ k,
                const float* __restrict__ v,
                const float* __restrict__ Si,
                const float* __restrict__ Zi,
                float* __restrict__ outV,    // [BN, M]
                float* __restrict__ outSi,   // [BN, D, M]
                float* __restrict__ outZi,   // [BN, D]
                int D, int M)
{
    const int bn  = blockIdx.x;
    const int tid = threadIdx.x;

    __shared__ float sQ[256];
    __shared__ float sK[256];
    __shared__ float swred[8];
    __shared__ float sZ;
    __shared__ float4 sacc[256];  // cross-d-group reduction buffer

    const size_t rowD = (size_t)bn * D;
    const size_t rowM = (size_t)bn * M;
    const size_t tile = (size_t)bn * D * M;

    // ---------------- Phase 1: feature maps + normalizer ----------------
    const int lane32 = tid & 31;
    const int warp   = tid >> 5;

    float part = 0.0f;
    for (int d = tid; d < D; d += blockDim.x) {
        float Qd = elu1(q[rowD + d]);
        float Kd = elu1(k[rowD + d]);
        float zn = Zi[rowD + d] + Kd;
        outZi[rowD + d] = zn;
        sQ[d] = Qd;
        sK[d] = Kd;
        part += Qd * zn;
    }
    #pragma unroll
    for (int o = 16; o > 0; o >>= 1)
        part += __shfl_down_sync(0xffffffffu, part, o);
    if (lane32 == 0) swred[warp] = part;
    __syncthreads();
    if (tid == 0) {
        float s = 0.0f;
        #pragma unroll
        for (int w = 0; w < 8; w++) s += swred[w];
        sZ = 1.0f / (s + RLA_EPS);
    }
    __syncthreads();
    const float Z = sZ;

    // ---------------- Phase 2: stream Si, rank-1 update, accumulate V ----
    const int M4   = M >> 2;       // float4 columns (64 for M=256)
    const int lane = tid & 63;     // m4 column within row
    const int ty   = tid >> 6;     // d-subgroup 0..3

    const float4* Si4 = (const float4*)(Si    + tile);
    float4*       So4 = (float4*)      (outSi + tile);
    const float4* v4p = (const float4*)(v     + rowM);
    float4*       V4  = (float4*)      (outV  + rowM);

    for (int m0 = 0; m0 < M4; m0 += 64) {
        const int m4 = m0 + lane;
        const bool act = (m4 < M4);

        float4 v4 = make_float4(0.f, 0.f, 0.f, 0.f);
        if (act) v4 = v4p[m4];

        float4 acc = make_float4(0.f, 0.f, 0.f, 0.f);

        if (act) {
            #pragma unroll 16
            for (int d = ty; d < D; d += 4) {
                const size_t idx = (size_t)d * M4 + m4;
                float4 s = __ldcs(&Si4[idx]);
                const float kd = sK[d];
                const float qd = sQ[d];
                s.x = fmaf(kd, v4.x, s.x);
                s.y = fmaf(kd, v4.y, s.y);
                s.z = fmaf(kd, v4.z, s.z);
                s.w = fmaf(kd, v4.w, s.w);
                So4[idx] = s;   // default caching: L2 write-coalescing
                acc.x = fmaf(qd, s.x, acc.x);
                acc.y = fmaf(qd, s.y, acc.y);
                acc.z = fmaf(qd, s.z, acc.z);
                acc.w = fmaf(qd, s.w, acc.w);
            }
        }

        sacc[tid] = acc;
        __syncthreads();
        if (ty == 0 && act) {
            float4 a0 = sacc[lane];
            float4 a1 = sacc[lane + 64];
            float4 a2 = sacc[lane + 128];
            float4 a3 = sacc[lane + 192];
            float4 out;
            out.x = Z * (a0.x + a1.x + a2.x + a3.x);
            out.y = Z * (a0.y + a1.y + a2.y + a3.y);
            out.z = Z * (a0.z + a1.z + a2.z + a3.z);
            out.w = Z * (a0.w + a1.w + a2.w + a3.w);
            V4[m4] = out;
        }
        __syncthreads();
    }
}

extern "C" void kernel_launch(void* const* d_in, const int* in_sizes, int n_in,
                              void* d_out, int out_size)
{
    const float* q  = (const float*)d_in[0];
    const float* k  = (const float*)d_in[1];
    const float* v  = (const float*)d_in[2];
    const float* Si = (const float*)d_in[3];
    const float* Zi = (const float*)d_in[4];

    const long long nQ  = in_sizes[0];  // BN * D
    const long long nV  = in_sizes[2];  // BN * M
    const long long nSi = in_sizes[3];  // BN * D * M

    const int D  = (int)(nSi / nV);
    const int M  = (int)(nSi / nQ);
    const int BN = (int)(nQ / D);

    float* out   = (float*)d_out;
    float* outV  = out;                 // [BN, M]
    float* outSi = out + nV;            // [BN, D, M]
    float* outZi = out + nV + nSi;      // [BN, D]

    rla_kernel<<<BN, 256>>>(q, k, v, Si, Zi, outV, outSi, outZi, D, M);
}